// round 10
// baseline (speedup 1.0000x reference)
#include <cuda_runtime.h>
#include <cstdint>

// IndRNN recurrent-only: h_t = relu(x_t + w * h_{t-1})
// x: [T=2048, B=64, H=512] f32. 512MB traffic floor.
// R8: R7 warp-specialized pipeline, extended to ALL 148 SMs with an
// 8-aligned column partition (136 CTAs x 56 cols + 12 x 48 -> 128B segments
// preserved), and U=32/NSTAGE=7 to halve mbarrier waits.
//   consumers: tid in [0, ncol)      LDS.128 + FMA chain + STG.128
//   producers: tid in [64, 64+ncol)  cp.async.cg 16B stream
// full/empty mbarrier ring, cp.async.mbarrier.arrive.noinc.

#define T_LEN 2048
#define B_DIM 64
#define H_DIM 512
#define NCH (B_DIM * H_DIM)       // 32768 chains
#define VEC 4
#define MAXCOL 56                 // smem column stride (max cols per CTA)
#define GRID 148
#define TPB 128
#define U 32                      // timesteps per stage
#define NSTAGE 7
#define NTILES (T_LEN / U)        // 64
#define STAGE_BYTES (U * MAXCOL * 16)                 // 28672
#define DATA_OFF 1024
#define SMEM_BYTES (DATA_OFF + NSTAGE * STAGE_BYTES)  // 201728

__device__ __forceinline__ void cp_async16(uint32_t saddr, const void* gptr) {
    asm volatile("cp.async.cg.shared.global [%0], [%1], 16;"
                 :: "r"(saddr), "l"(gptr));
}

__device__ __forceinline__ void mbar_init(uint32_t addr, uint32_t cnt) {
    asm volatile("mbarrier.init.shared.b64 [%0], %1;" :: "r"(addr), "r"(cnt) : "memory");
}

__device__ __forceinline__ void mbar_arrive(uint32_t addr) {
    asm volatile("mbarrier.arrive.shared.b64 _, [%0];" :: "r"(addr) : "memory");
}

__device__ __forceinline__ void cp_async_mbar_arrive(uint32_t addr) {
    asm volatile("cp.async.mbarrier.arrive.noinc.shared.b64 [%0];" :: "r"(addr) : "memory");
}

__device__ __forceinline__ void mbar_wait(uint32_t addr, uint32_t p) {
    uint32_t done;
    asm volatile(
        "{\n\t.reg .pred q;\n\t"
        "mbarrier.try_wait.parity.acquire.cta.shared::cta.b64 q, [%1], %2;\n\t"
        "selp.b32 %0, 1, 0, q;\n\t}"
        : "=r"(done) : "r"(addr), "r"(p) : "memory");
    if (!done) {
        asm volatile(
            "{\n\t.reg .pred q;\n\t"
            "WL_%=:\n\t"
            "mbarrier.try_wait.parity.acquire.cta.shared::cta.b64 q, [%0], %1, 0x989680;\n\t"
            "@q bra.uni WD_%=;\n\t"
            "bra.uni WL_%=;\n\t"
            "WD_%=:\n\t}"
            :: "r"(addr), "r"(p) : "memory");
    }
}

__global__ __launch_bounds__(TPB, 1)
void indrnn_scan_kernel(const float* __restrict__ x,
                        const float* __restrict__ w,
                        float* __restrict__ out) {
    extern __shared__ char smem[];
    const uint32_t sbase = (uint32_t)__cvta_generic_to_shared(smem);
    const uint32_t bar = sbase;              // full[s]@s*16, empty[s]@s*16+8
    const uint32_t data = sbase + DATA_OFF;

    const int tid = threadIdx.x;
    const int cta = blockIdx.x;

    // 8-aligned column partition: CTAs 0..135 -> 56 cols, 136..147 -> 48 cols.
    const int big   = (cta < 136);
    const int ncol  = big ? 56 : 48;
    const int base  = big ? cta * 56 : (136 * 56 + (cta - 136) * 48);

    if (tid == 0) {
        #pragma unroll
        for (int s = 0; s < NSTAGE; ++s) {
            mbar_init(bar + s * 16,     (uint32_t)ncol);  // full
            mbar_init(bar + s * 16 + 8, (uint32_t)ncol);  // empty
        }
    }
    __syncthreads();

    const int stride4 = NCH / VEC;           // 8192 float4 per timestep

    if (tid >= 64) {
        // ---------------- Producer ----------------
        const int col = tid - 64;
        if (col >= ncol) return;
        const int cid = base + col;
        const float4* xp = reinterpret_cast<const float4*>(x) + cid;
        int stage = 0, phase = 1;            // first empty-wait passes
        for (int tile = 0; tile < NTILES; ++tile) {
            mbar_wait(bar + stage * 16 + 8, phase);
            const float4* g = xp + (size_t)tile * U * stride4;
            const uint32_t sb = data + (uint32_t)stage * STAGE_BYTES + (uint32_t)col * 16u;
            #pragma unroll
            for (int u = 0; u < U; ++u)
                cp_async16(sb + (uint32_t)(u * MAXCOL) * 16u,
                           g + (size_t)u * stride4);
            cp_async_mbar_arrive(bar + stage * 16);
            if (++stage == NSTAGE) { stage = 0; phase ^= 1; }
        }
    } else {
        // ---------------- Consumer ----------------
        const int col = tid;
        if (col >= ncol) return;
        const int cid = base + col;
        const float4 wv = *reinterpret_cast<const float4*>(
            w + ((cid & (H_DIM / VEC - 1)) << 2));
        float4* op = reinterpret_cast<float4*>(out) + cid;
        float4 h = make_float4(0.f, 0.f, 0.f, 0.f);

        int stage = 0, phase = 0;
        for (int tile = 0; tile < NTILES; ++tile) {
            mbar_wait(bar + stage * 16, phase);
            const float4* sp = reinterpret_cast<const float4*>(
                smem + DATA_OFF + (size_t)stage * STAGE_BYTES) + col;
            float4* ob = op + (size_t)tile * U * stride4;
            #pragma unroll
            for (int u = 0; u < U; ++u) {
                float4 v = sp[(size_t)u * MAXCOL];
                h.x = fmaxf(fmaf(wv.x, h.x, v.x), 0.0f);
                h.y = fmaxf(fmaf(wv.y, h.y, v.y), 0.0f);
                h.z = fmaxf(fmaf(wv.z, h.z, v.z), 0.0f);
                h.w = fmaxf(fmaf(wv.w, h.w, v.w), 0.0f);
                __stcs(ob + (size_t)u * stride4, h);
            }
            mbar_arrive(bar + stage * 16 + 8);
            if (++stage == NSTAGE) { stage = 0; phase ^= 1; }
        }
    }
}

extern "C" void kernel_launch(void* const* d_in, const int* in_sizes, int n_in,
                              void* d_out, int out_size) {
    const float* x = (const float*)d_in[0];
    const float* w = (const float*)d_in[1];
    float* out = (float*)d_out;

    cudaFuncSetAttribute(indrnn_scan_kernel,
                         cudaFuncAttributeMaxDynamicSharedMemorySize, SMEM_BYTES);

    indrnn_scan_kernel<<<GRID, TPB, SMEM_BYTES>>>(x, w, out);
}

// round 11
// speedup vs baseline: 1.0681x; 1.0681x over previous
#include <cuda_runtime.h>
#include <cstdint>

// IndRNN recurrent-only: h_t = relu(x_t + w * h_{t-1})
// x: [T=2048, B=64, H=512] f32. 512MB traffic floor.
// R11: revert to R7's proven layout (128 CTAs x 64 float4-cols, TPB=128,
// warp-specialized producer/consumer, mbarrier ring) but U=32 / NSTAGE=6:
// same 192-timestep in-flight depth, HALF the mbarrier waits + loop overhead.
//   consumers: tid 0..63    LDS.128 + FMA chain + STG.128 (.cs)
//   producers: tid 64..127  cp.async.cg 16B stream, arrive via noinc.

#define T_LEN 2048
#define B_DIM 64
#define H_DIM 512
#define NCH (B_DIM * H_DIM)       // 32768 chains
#define VEC 4
#define COLS_PER_CTA 64
#define GRID 128
#define TPB 128
#define U 32                      // timesteps per stage
#define NSTAGE 6
#define NTILES (T_LEN / U)        // 64
#define STAGE_BYTES (U * COLS_PER_CTA * 16)           // 32768
#define DATA_OFF 1024
#define SMEM_BYTES (DATA_OFF + NSTAGE * STAGE_BYTES)  // 197632

__device__ __forceinline__ void cp_async16(uint32_t saddr, const void* gptr) {
    asm volatile("cp.async.cg.shared.global [%0], [%1], 16;"
                 :: "r"(saddr), "l"(gptr));
}

__device__ __forceinline__ void mbar_init(uint32_t addr, uint32_t cnt) {
    asm volatile("mbarrier.init.shared.b64 [%0], %1;" :: "r"(addr), "r"(cnt) : "memory");
}

__device__ __forceinline__ void mbar_arrive(uint32_t addr) {
    asm volatile("mbarrier.arrive.shared.b64 _, [%0];" :: "r"(addr) : "memory");
}

__device__ __forceinline__ void cp_async_mbar_arrive(uint32_t addr) {
    asm volatile("cp.async.mbarrier.arrive.noinc.shared.b64 [%0];" :: "r"(addr) : "memory");
}

__device__ __forceinline__ void mbar_wait(uint32_t addr, uint32_t p) {
    uint32_t done;
    asm volatile(
        "{\n\t.reg .pred q;\n\t"
        "mbarrier.try_wait.parity.acquire.cta.shared::cta.b64 q, [%1], %2;\n\t"
        "selp.b32 %0, 1, 0, q;\n\t}"
        : "=r"(done) : "r"(addr), "r"(p) : "memory");
    if (!done) {
        asm volatile(
            "{\n\t.reg .pred q;\n\t"
            "WL_%=:\n\t"
            "mbarrier.try_wait.parity.acquire.cta.shared::cta.b64 q, [%0], %1, 0x989680;\n\t"
            "@q bra.uni WD_%=;\n\t"
            "bra.uni WL_%=;\n\t"
            "WD_%=:\n\t}"
            :: "r"(addr), "r"(p) : "memory");
    }
}

__global__ __launch_bounds__(TPB, 1)
void indrnn_scan_kernel(const float* __restrict__ x,
                        const float* __restrict__ w,
                        float* __restrict__ out) {
    extern __shared__ char smem[];
    const uint32_t sbase = (uint32_t)__cvta_generic_to_shared(smem);
    const uint32_t bar = sbase;              // full[s]@s*16, empty[s]@s*16+8
    const uint32_t data = sbase + DATA_OFF;

    const int tid = threadIdx.x;

    if (tid == 0) {
        #pragma unroll
        for (int s = 0; s < NSTAGE; ++s) {
            mbar_init(bar + s * 16,     COLS_PER_CTA);  // full: 64 producer arrivals
            mbar_init(bar + s * 16 + 8, COLS_PER_CTA);  // empty: 64 consumer arrivals
        }
    }
    __syncthreads();

    const int stride4 = NCH / VEC;                    // 8192 float4 per timestep
    const int col = tid & 63;
    const int cid = blockIdx.x * COLS_PER_CTA + col;  // global float4 column

    if (tid >= 64) {
        // ---------------- Producer: stream x column via cp.async ----------------
        const float4* xp = reinterpret_cast<const float4*>(x) + cid;
        int stage = 0, phase = 1;                     // first empty-wait passes
        for (int tile = 0; tile < NTILES; ++tile) {
            mbar_wait(bar + stage * 16 + 8, phase);   // wait empty
            const float4* g = xp + (size_t)tile * U * stride4;
            const uint32_t sb = data + (uint32_t)stage * STAGE_BYTES + (uint32_t)col * 16u;
            #pragma unroll
            for (int u = 0; u < U; ++u)
                cp_async16(sb + (uint32_t)(u * COLS_PER_CTA) * 16u,
                           g + (size_t)u * stride4);
            cp_async_mbar_arrive(bar + stage * 16);   // async arrive on full
            if (++stage == NSTAGE) { stage = 0; phase ^= 1; }
        }
    } else {
        // ---------------- Consumer: recurrence + store ----------------
        const float4 wv = *reinterpret_cast<const float4*>(
            w + ((cid & (H_DIM / VEC - 1)) << 2));
        float4* op = reinterpret_cast<float4*>(out) + cid;
        float4 h = make_float4(0.f, 0.f, 0.f, 0.f);

        int stage = 0, phase = 0;
        for (int tile = 0; tile < NTILES; ++tile) {
            mbar_wait(bar + stage * 16, phase);       // wait full
            const float4* sp = reinterpret_cast<const float4*>(
                smem + DATA_OFF + (size_t)stage * STAGE_BYTES) + col;
            float4* ob = op + (size_t)tile * U * stride4;
            #pragma unroll
            for (int u = 0; u < U; ++u) {
                float4 v = sp[(size_t)u * COLS_PER_CTA];
                h.x = fmaxf(fmaf(wv.x, h.x, v.x), 0.0f);
                h.y = fmaxf(fmaf(wv.y, h.y, v.y), 0.0f);
                h.z = fmaxf(fmaf(wv.z, h.z, v.z), 0.0f);
                h.w = fmaxf(fmaf(wv.w, h.w, v.w), 0.0f);
                __stcs(ob + (size_t)u * stride4, h);
            }
            mbar_arrive(bar + stage * 16 + 8);        // release stage
            if (++stage == NSTAGE) { stage = 0; phase ^= 1; }
        }
    }
}

extern "C" void kernel_launch(void* const* d_in, const int* in_sizes, int n_in,
                              void* d_out, int out_size) {
    const float* x = (const float*)d_in[0];
    const float* w = (const float*)d_in[1];
    float* out = (float*)d_out;

    cudaFuncSetAttribute(indrnn_scan_kernel,
                         cudaFuncAttributeMaxDynamicSharedMemorySize, SMEM_BYTES);

    indrnn_scan_kernel<<<GRID, TPB, SMEM_BYTES>>>(x, w, out);
}